// round 10
// baseline (speedup 1.0000x reference)
#include <cuda_runtime.h>
#include <cuda_bf16.h>
#include <cuda_fp16.h>
#include <math.h>

#define N_IN   12288
#define H0     256
#define BATCH  8192
#define RPB    16                 // rows per fused block (one per warp)
#define O0_STRIDE 520             // halves per smem o0 row

// Scratch (static device allocations are allowed)
__device__ __half g_ft_wt_h[N_IN * H0];   // (12288, 256) transposed, fp16
__device__ uint2  g_w1bf[4096];           // w1 B-fragments [(kc*4+nt)*32+lane]
__device__ float  g_w2t[32 * 32];         // l2_w transposed [i][h2]
__device__ int    g_side_mode;            // 0=uint8, 1=int32, 2=float32

__device__ __forceinline__ unsigned smem_u32(const void* p) {
    unsigned a;
    asm("{ .reg .u64 t; cvta.to.shared.u64 t, %1; cvt.u32.u64 %0, t; }"
        : "=r"(a) : "l"(p));
    return a;
}

// ---------------------------------------------------------------------------
// Combined transpose + prep, grid (385, 8), block (32, 32) = 1024 threads.
//  - blocks x<384: tiled transpose+fp16 of ft_w into g_ft_wt_h
//  - blocks x==384 (8 of them, indexed by y):
//      y-th block builds 512 of the 4096 w1 B-fragments
//      y==0 also does the w2 transpose; y==7 also does the side sniff
// B frag (m16n8k16 col-major B): lane holds
//   .x = half2(B[k0][n], B[k0+1][n]), .y = half2(B[k0+8][n], B[k0+9][n])
// k0 = kc*16 + (lane%4)*2, n = nt*8 + lane/4; B[k][n] = l1_w[n*512 + k].
// ---------------------------------------------------------------------------
__global__ void transpose_prep_kernel(const float* __restrict__ ft_w,
                                      const unsigned char* __restrict__ p,
                                      const float* __restrict__ l1w,
                                      const float* __restrict__ l2w) {
    if (blockIdx.x < 384) {
        __shared__ float tile[32][33];
        int f = blockIdx.x * 32 + threadIdx.x;
        int h = blockIdx.y * 32 + threadIdx.y;
        tile[threadIdx.y][threadIdx.x] = ft_w[h * N_IN + f];
        __syncthreads();
        int oh = blockIdx.y * 32 + threadIdx.x;
        int of = blockIdx.x * 32 + threadIdx.y;
        g_ft_wt_h[of * H0 + oh] = __float2half_rn(tile[threadIdx.x][threadIdx.y]);
        return;
    }

    int tid = threadIdx.y * 32 + threadIdx.x;   // 0..1023
    int blk = blockIdx.y;                        // 0..7

    // w1 fragments: 512 per block, threads 0..511
    if (tid < 512) {
        int idx  = blk * 512 + tid;              // 0..4095
        int lane = idx & 31;
        int t    = idx >> 5;
        int nt   = t & 3;
        int kc   = t >> 2;
        int k0   = kc * 16 + (lane & 3) * 2;
        int n    = nt * 8 + (lane >> 2);
        __half2 x = __floats2half2_rn(l1w[n * 512 + k0],     l1w[n * 512 + k0 + 1]);
        __half2 y = __floats2half2_rn(l1w[n * 512 + k0 + 8], l1w[n * 512 + k0 + 9]);
        uint2 v;
        v.x = *(unsigned*)&x;
        v.y = *(unsigned*)&y;
        g_w1bf[idx] = v;
    }
    // w2 transpose: block y==0
    if (blk == 0) {
        int h2 = tid >> 5, i = tid & 31;
        g_w2t[i * 32 + h2] = l2w[h2 * 32 + i];
    }
    // side sniff: block y==7
    if (blk == 7) {
        __shared__ int c3F, cOdd;
        if (tid == 0) { c3F = 0; cOdd = 0; }
        __syncthreads();
        int l3f = 0, lodd = 0;
        for (int i = tid; i < 8192; i += 1024) {
            unsigned char b = p[i];
            if ((i & 3) == 3 && b == 0x3F) l3f++;
            if ((i & 3) != 0 && b != 0)    lodd++;
        }
        atomicAdd(&c3F, l3f);
        atomicAdd(&cOdd, lodd);
        __syncthreads();
        if (tid == 0)
            g_side_mode = (c3F > 0) ? 2 : ((cOdd > 0) ? 0 : 1);
    }
}

// ---------------------------------------------------------------------------
// Sparse gather-accumulate (scan): fp16 columns, fp32 accumulation.
// h mapping: acc[j] <-> h = lane*8 + j
// ---------------------------------------------------------------------------
__device__ __forceinline__ void accum_mask(unsigned mask, int fbase, int lane,
                                           float acc[8]) {
    while (mask) {
        int b = __ffs(mask) - 1;
        mask &= mask - 1;
        int f = fbase + b * 4;
        const uint4* wp = (const uint4*)(g_ft_wt_h + (size_t)f * H0);
        uint4 a = __ldg(wp + lane);
        const __half2* hp = (const __half2*)&a;
        float2 f0 = __half22float2(hp[0]);
        float2 f1 = __half22float2(hp[1]);
        float2 f2 = __half22float2(hp[2]);
        float2 f3 = __half22float2(hp[3]);
        acc[0] += f0.x; acc[1] += f0.y;
        acc[2] += f1.x; acc[3] += f1.y;
        acc[4] += f2.x; acc[5] += f2.y;
        acc[6] += f3.x; acc[7] += f3.y;
    }
}

__device__ __forceinline__ void process_chunk(const float4 v[4], int base,
                                              int lane, float acc[8]) {
    #pragma unroll
    for (int c = 0; c < 4; c++) {
        int cb = base + c * 128;
        float s = v[c].x + v[c].y + v[c].z + v[c].w;
        unsigned any = __ballot_sync(0xffffffffu, s != 0.0f);
        if (any) {
            unsigned mx = __ballot_sync(0xffffffffu, v[c].x != 0.0f);
            unsigned my = __ballot_sync(0xffffffffu, v[c].y != 0.0f);
            unsigned mz = __ballot_sync(0xffffffffu, v[c].z != 0.0f);
            unsigned mw = __ballot_sync(0xffffffffu, v[c].w != 0.0f);
            accum_mask(mx, cb + 0, lane, acc);
            accum_mask(my, cb + 1, lane, acc);
            accum_mask(mz, cb + 2, lane, acc);
            accum_mask(mw, cb + 3, lane, acc);
        }
    }
}

// ---------------------------------------------------------------------------
// Fused kernel: 16 warps scan 16 rows -> smem o0 -> tensor-core tail.
// Tail warps read w1 fragments / w2 / biases DIRECTLY from global (L2-hot).
// smem: o0 (16*520 f16 = 16640B) | o1 (16*33 f32 = 2112B)
// ---------------------------------------------------------------------------
__global__ __launch_bounds__(512, 2) void nnue_fused_kernel(
    const float* __restrict__ white, const float* __restrict__ black,
    const void* __restrict__ side, const float* __restrict__ ft_b,
    const float* __restrict__ l1_b, const float* __restrict__ l2_b,
    const float* __restrict__ l3_w, const float* __restrict__ l3_b,
    float* __restrict__ out)
{
    extern __shared__ char smraw[];
    __half* o0s = (__half*)smraw;                  // 16640B
    float*  o1s = (float*)(smraw + 16640);         // 2112B

    int tid  = threadIdx.x;
    int lane = tid & 31;
    int wid  = tid >> 5;

    // ---- Scan: warp wid handles row r
    int r = blockIdx.x * RPB + wid;

    float4 b0 = __ldg((const float4*)ft_b + lane * 2);
    float4 b1 = __ldg((const float4*)ft_b + lane * 2 + 1);
    float aw[8] = {b0.x, b0.y, b0.z, b0.w, b1.x, b1.y, b1.z, b1.w};
    float ab[8] = {b0.x, b0.y, b0.z, b0.w, b1.x, b1.y, b1.z, b1.w};

    const float4* wrow = (const float4*)(white + (size_t)r * N_IN);
    const float4* brow = (const float4*)(black + (size_t)r * N_IN);

    for (int base = 0; base < N_IN; base += 512) {
        int q = (base >> 2) + lane;
        float4 wv[4], bv[4];
        #pragma unroll
        for (int c = 0; c < 4; c++) wv[c] = __ldcs(wrow + q + c * 32);
        #pragma unroll
        for (int c = 0; c < 4; c++) bv[c] = __ldcs(brow + q + c * 32);
        process_chunk(wv, base, lane, aw);
        process_chunk(bv, base, lane, ab);
    }

    int mode = g_side_mode;
    bool s;
    if (mode == 0)      s = ((const unsigned char*)side)[r] != 0;
    else if (mode == 1) s = ((const int*)side)[r] != 0;
    else                s = ((const float*)side)[r] != 0.0f;

    float us[8], th[8];
    #pragma unroll
    for (int j = 0; j < 8; j++) {
        float u = s ? aw[j] : ab[j];
        float t = s ? ab[j] : aw[j];
        us[j] = fminf(fmaxf(u, 0.0f), 1.0f);
        th[j] = fminf(fmaxf(t, 0.0f), 1.0f);
    }
    // write o0 row (fp16) to smem: halves [lane*8 .. +8) and [256+lane*8 ..)
    {
        __half2 u0 = __floats2half2_rn(us[0], us[1]);
        __half2 u1 = __floats2half2_rn(us[2], us[3]);
        __half2 u2 = __floats2half2_rn(us[4], us[5]);
        __half2 u3 = __floats2half2_rn(us[6], us[7]);
        __half2 t0 = __floats2half2_rn(th[0], th[1]);
        __half2 t1 = __floats2half2_rn(th[2], th[3]);
        __half2 t2 = __floats2half2_rn(th[4], th[5]);
        __half2 t3 = __floats2half2_rn(th[6], th[7]);
        uint4 pu, pt;
        pu.x = *(unsigned*)&u0; pu.y = *(unsigned*)&u1;
        pu.z = *(unsigned*)&u2; pu.w = *(unsigned*)&u3;
        pt.x = *(unsigned*)&t0; pt.y = *(unsigned*)&t1;
        pt.z = *(unsigned*)&t2; pt.w = *(unsigned*)&t3;
        uint4* orow = (uint4*)(o0s + wid * O0_STRIDE);   // 65 uint4 per row
        orow[lane]      = pu;
        orow[32 + lane] = pt;
    }
    __syncthreads();

    // ---- L1 via tensor cores: warps 0-3, warp nt owns n-tile nt (cols nt*8..+7)
    if (wid < 4) {
        int nt = wid;
        int arow = (lane & 7) + ((lane >> 3) & 1) * 8;
        int akof = ((lane >> 4) & 1) * 8;
        unsigned abase = smem_u32(o0s) + (arow * O0_STRIDE + akof) * 2;

        float c[4] = {0.f, 0.f, 0.f, 0.f};
        #pragma unroll 4
        for (int kc = 0; kc < 32; kc++) {
            unsigned a0, a1, a2, a3;
            asm volatile(
                "ldmatrix.sync.aligned.m8n8.x4.shared.b16 {%0,%1,%2,%3}, [%4];"
                : "=r"(a0), "=r"(a1), "=r"(a2), "=r"(a3)
                : "r"(abase + kc * 32));
            uint2 bB = __ldg(g_w1bf + (kc * 4 + nt) * 32 + lane);
            asm volatile(
                "mma.sync.aligned.m16n8k16.row.col.f32.f16.f16.f32 "
                "{%0,%1,%2,%3}, {%4,%5,%6,%7}, {%8,%9}, {%0,%1,%2,%3};"
                : "+f"(c[0]), "+f"(c[1]), "+f"(c[2]), "+f"(c[3])
                : "r"(a0), "r"(a1), "r"(a2), "r"(a3), "r"(bB.x), "r"(bB.y));
        }
        // epilogue: bias + clip -> o1s
        int rloc = lane >> 2;
        int col  = nt * 8 + (lane & 3) * 2;
        float bc0 = __ldg(l1_b + col), bc1 = __ldg(l1_b + col + 1);
        o1s[rloc * 33 + col]           = fminf(fmaxf(c[0] + bc0, 0.f), 1.f);
        o1s[rloc * 33 + col + 1]       = fminf(fmaxf(c[1] + bc1, 0.f), 1.f);
        o1s[(rloc + 8) * 33 + col]     = fminf(fmaxf(c[2] + bc0, 0.f), 1.f);
        o1s[(rloc + 8) * 33 + col + 1] = fminf(fmaxf(c[3] + bc1, 0.f), 1.f);
    }
    __syncthreads();

    // ---- L2/L3: warps 0-1, warp w rows w*8..w*8+7, lane = h2
    if (wid < 2) {
        float acc2[8];
        float bias2 = __ldg(l2_b + lane);
        #pragma unroll
        for (int k = 0; k < 8; k++) acc2[k] = bias2;
        #pragma unroll 4
        for (int hh = 0; hh < 32; hh++) {
            float wv = __ldg(g_w2t + hh * 32 + lane);
            #pragma unroll
            for (int k = 0; k < 8; k++)
                acc2[k] = fmaf(o1s[(wid * 8 + k) * 33 + hh], wv, acc2[k]);
        }
        float lw = __ldg(l3_w + lane);
        float l3b = __ldg(l3_b);
        float p[8];
        #pragma unroll
        for (int k = 0; k < 8; k++)
            p[k] = fminf(fmaxf(acc2[k], 0.f), 1.f) * lw;
        #pragma unroll
        for (int off = 16; off; off >>= 1) {
            #pragma unroll
            for (int k = 0; k < 8; k++)
                p[k] += __shfl_xor_sync(0xffffffffu, p[k], off);
        }
        if (lane < 8) {
            float t = (p[lane] + l3b) * 1.5f;   // OUTPUT_SCALE / WDL_SCALE
            out[blockIdx.x * RPB + wid * 8 + lane] = 1.0f / (1.0f + expf(-t));
        }
    }
}

// ---------------------------------------------------------------------------
extern "C" void kernel_launch(void* const* d_in, const int* in_sizes, int n_in,
                              void* d_out, int out_size) {
    const float* white = (const float*)d_in[0];
    const float* black = (const float*)d_in[1];
    const void*  side  = d_in[2];
    const float* ft_w  = (const float*)d_in[3];
    const float* ft_b  = (const float*)d_in[4];
    const float* l1_w  = (const float*)d_in[5];
    const float* l1_b  = (const float*)d_in[6];
    const float* l2_w  = (const float*)d_in[7];
    const float* l2_b  = (const float*)d_in[8];
    const float* l3_w  = (const float*)d_in[9];
    const float* l3_b  = (const float*)d_in[10];
    float* out = (float*)d_out;

    const int fused_smem = 16640 + 2112 + 128;   // ~18.9 KB
    cudaFuncSetAttribute(nnue_fused_kernel,
                         cudaFuncAttributeMaxDynamicSharedMemorySize,
                         fused_smem);

    transpose_prep_kernel<<<dim3(385, 8), dim3(32, 32)>>>(
        ft_w, (const unsigned char*)side, l1_w, l2_w);
    nnue_fused_kernel<<<BATCH / RPB, 512, fused_smem>>>(
        white, black, side, ft_b, l1_b, l2_b, l3_w, l3_b, out);
}